// round 14
// baseline (speedup 1.0000x reference)
#include <cuda_runtime.h>
#include <cuda_fp16.h>
#include <math.h>
#include <stdint.h>

// ---------------- problem constants ----------------
#define Bb 2
#define Tt 2048
#define Dd 1024
#define Hh 8
#define DK 128
#define DV 256
#define NH 2
#define INTER 2816
#define BT (Bb*Tt)              // 4096
#define NQKVG 9216              // 1024 + 2048 + 4096 + 2048

// ---------------- scratch (device globals; no allocation allowed) ----------
__device__ float g_x   [(size_t)BT*Dd];
__device__ float g_qkvg[(size_t)BT*NQKVG];
__device__ float g_q   [(size_t)BT*Hh*DK];
__device__ float g_k   [(size_t)BT*NH*Hh*DK];
__device__ float g_v   [(size_t)BT*NH*Hh*DV];
__device__ float g_beta[(size_t)BT*Hh*NH];
__device__ float g_gdec[(size_t)BT*Hh];
__device__ float g_o   [(size_t)BT*Hh*DV];
__device__ float g_hid [(size_t)BT*Dd];

// fp16 buffers (activations: [M, K]; weights transposed: [N, K])
__device__ __half g2_x    [(size_t)BT*1024];
__device__ __half g2_y    [(size_t)BT*1024];
__device__ __half g2_o    [(size_t)BT*2048];
__device__ __half g2_mlp  [(size_t)BT*2816];
__device__ __half g2_Wqkvg[(size_t)NQKVG*1024];
__device__ __half g2_Wo   [(size_t)1024*2048];
__device__ __half g2_Wgate[(size_t)5632*1024];
__device__ __half g2_Wdown[(size_t)1024*2816];

// ---------------- helpers ----------------
__device__ __forceinline__ uint32_t smem_u32(const void* p){
    uint32_t a;
    asm("{ .reg .u64 t; cvta.to.shared.u64 t, %1; cvt.u32.u64 %0, t; }" : "=r"(a) : "l"(p));
    return a;
}
__device__ __forceinline__ void cp16(uint32_t s, const void* g){
    asm volatile("cp.async.cg.shared.global [%0], [%1], 16;" :: "r"(s), "l"(g) : "memory");
}
__device__ __forceinline__ void ldm4(uint32_t* d, uint32_t addr){
    asm volatile("ldmatrix.sync.aligned.m8n8.x4.shared.b16 {%0,%1,%2,%3}, [%4];"
        : "=r"(d[0]), "=r"(d[1]), "=r"(d[2]), "=r"(d[3]) : "r"(addr));
}
__device__ __forceinline__ void mma16816(float* d, const uint32_t* a, const uint32_t* b){
    asm volatile("mma.sync.aligned.m16n8k16.row.col.f32.f16.f16.f32 "
        "{%0,%1,%2,%3}, {%4,%5,%6,%7}, {%8,%9}, {%0,%1,%2,%3};"
        : "+f"(d[0]), "+f"(d[1]), "+f"(d[2]), "+f"(d[3])
        : "r"(a[0]), "r"(a[1]), "r"(a[2]), "r"(a[3]), "r"(b[0]), "r"(b[1]));
}
__device__ __forceinline__ float sigmoidf_(float x){ return 1.f/(1.f+expf(-x)); }
__device__ __forceinline__ float siluf_(float x){ return x*sigmoidf_(x); }

__device__ __forceinline__ float block_reduce_sum(float v, float* sh){
    int lane = threadIdx.x & 31, warp = threadIdx.x >> 5;
    #pragma unroll
    for (int m=16;m;m>>=1) v += __shfl_xor_sync(0xffffffffu, v, m);
    if (lane==0) sh[warp]=v;
    __syncthreads();
    int nw = (blockDim.x+31)>>5;
    float t = 0.f;
    #pragma unroll
    for (int i=0;i<8;i++) if (i<nw) t += sh[i];
    return t;
}

// ---------------- rmsnorm (optionally emits fp32 and/or fp16) --------------
__global__ void rmsnorm_kernel(const float* __restrict__ in, const float* __restrict__ w,
                               float* __restrict__ out32, __half* __restrict__ out2,
                               int D){
    __shared__ float sh[8];
    int row = blockIdx.x;
    const float* xr = in + (size_t)row*D;
    float ss = 0.f;
    for (int d=threadIdx.x; d<D; d+=blockDim.x){ float v=xr[d]; ss += v*v; }
    float tot = block_reduce_sum(ss, sh);
    float scale = rsqrtf(tot/(float)D + 1e-6f);
    for (int d=threadIdx.x; d<D; d+=blockDim.x){
        float v = xr[d]*scale*w[d];
        if (out32) out32[(size_t)row*D + d] = v;
        if (out2)  out2[(size_t)row*D + d] = __float2half_rn(v);
    }
}

// ---------------- weight [K,N] fp32 -> transposed [N,K] fp16 ---------------
__global__ void w3_kernel(const float* __restrict__ W, __half* __restrict__ B2, int K, int N){
    __shared__ float tile[32][33];
    int n0 = blockIdx.x*32, k0 = blockIdx.y*32;
    int tx = threadIdx.x & 31, ty = threadIdx.x >> 5;
    #pragma unroll
    for (int i=0;i<4;i++)
        tile[ty + i*8][tx] = W[(size_t)(k0 + ty + i*8)*N + n0 + tx];
    __syncthreads();
    #pragma unroll
    for (int i=0;i<4;i++){
        int n = n0 + ty + i*8;
        float v = tile[tx][ty + i*8];
        B2[(size_t)n*K + k0 + tx] = __float2half_rn(v);
    }
}

// -------- Wgate [K,5632] -> interleaved transposed [5632,K] fp16 -----------
__global__ void w3i_kernel(const float* __restrict__ W, __half* __restrict__ B2, int K, int N){
    __shared__ float tile[32][33];
    int n0 = blockIdx.x*32, k0 = blockIdx.y*32;
    int j0 = n0 >> 1, N2 = N >> 1;
    int tx = threadIdx.x & 31, ty = threadIdx.x >> 5;
    int srccol = (tx < 16) ? (j0 + tx) : (N2 + j0 + (tx - 16));
    #pragma unroll
    for (int i=0;i<4;i++)
        tile[ty + i*8][tx] = W[(size_t)(k0 + ty + i*8)*N + srccol];
    __syncthreads();
    #pragma unroll
    for (int i=0;i<4;i++){
        int r = ty + i*8;
        int n = n0 + r;
        float v = tile[tx][(r&1)*16 + (r>>1)];
        B2[(size_t)n*K + k0 + tx] = __float2half_rn(v);
    }
}

// ---------------- fp16 mma.sync GEMM: 128x128, 256 thr, 4 stages, 2 CTA/SM -
#define BKg   32
#define STG   4
#define ROWB  80
#define ATILE (128*ROWB)
#define STILE (2*ATILE)
#define GEMM_SMEM (STG*STILE)

__global__ void __launch_bounds__(256,2) mma_gemm(
        const __half* __restrict__ A, const __half* __restrict__ B,
        float* __restrict__ C, const float* __restrict__ addsrc,
        __half* __restrict__ out2,
        int M, int N, int Kp){
    extern __shared__ char smem[];
    int tid = threadIdx.x;
    int bm = blockIdx.y*128, bn = blockIdx.x*128;
    uint32_t sbase = smem_u32(smem);

    int lane = tid & 31, wid = tid >> 5;
    int warpM = wid >> 1, warpN = wid & 1;
    int g = lane >> 2, tg = lane & 3;
    int q8 = lane >> 3, r8 = lane & 7;

    const char* gAb = (const char*)(A + (size_t)bm*Kp);
    const char* gBb = (const char*)(B + (size_t)bn*Kp);
    int ldr = tid >> 2, ldc = tid & 3;
    const int nch = Kp / BKg;

    #define ISSUE(chunk, slot) do { \
        uint32_t sA_ = sbase + (slot)*STILE; \
        uint32_t sB_ = sA_ + ATILE; \
        size_t kof = (size_t)(chunk)*BKg*2; \
        _Pragma("unroll") \
        for (int i_=0;i_<2;i_++){ \
            int row_ = ldr + i_*64; \
            cp16(sA_ + row_*ROWB + ldc*16, gAb + (size_t)row_*Kp*2 + kof + ldc*16); \
            cp16(sB_ + row_*ROWB + ldc*16, gBb + (size_t)row_*Kp*2 + kof + ldc*16); \
        } \
        asm volatile("cp.async.commit_group;" ::: "memory"); \
    } while(0)

    float acc[2][8][4];
    #pragma unroll
    for (int mt=0;mt<2;mt++)
        #pragma unroll
        for (int nt=0;nt<8;nt++)
            #pragma unroll
            for (int i=0;i<4;i++) acc[mt][nt][i]=0.f;

    ISSUE(0,0);
    ISSUE(1,1);
    ISSUE(2,2);

    for (int c=0; c<nch; c++){
        asm volatile("cp.async.wait_group 2;" ::: "memory");
        __syncthreads();
        if (c+3 < nch) ISSUE(c+3, (c+3)&3);
        else asm volatile("cp.async.commit_group;" ::: "memory");

        uint32_t sA = sbase + (c&3)*STILE;
        uint32_t sB = sA + ATILE;
        #pragma unroll
        for (int ks=0; ks<2; ks++){
            uint32_t a[2][4], b[4][4];
            #pragma unroll
            for (int mt=0;mt<2;mt++){
                uint32_t addr = sA + (uint32_t)((warpM*32 + mt*16 + (q8&1)*8 + r8)*ROWB
                                + ks*32 + (q8>>1)*16);
                ldm4(a[mt], addr);
            }
            #pragma unroll
            for (int pr=0;pr<4;pr++){
                uint32_t addr = sB + (uint32_t)((warpN*64 + pr*16 + (q8>>1)*8 + r8)*ROWB
                                + ks*32 + (q8&1)*16);
                ldm4(b[pr], addr);
            }
            #pragma unroll
            for (int mt=0;mt<2;mt++)
                #pragma unroll
                for (int nt=0;nt<8;nt++)
                    mma16816(acc[mt][nt], a[mt], &b[nt>>1][(nt&1)*2]);
        }
    }

    if (out2){
        int halfN = N >> 1;                     // = INTER
        #pragma unroll
        for (int mt=0;mt<2;mt++){
            int r0 = bm + warpM*32 + mt*16 + g;
            #pragma unroll
            for (int nt=0;nt<8;nt++){
                int col = bn + warpN*64 + nt*8 + tg*2;
                int j = col >> 1;
                float v0 = siluf_(acc[mt][nt][0])*acc[mt][nt][1];
                float v1 = siluf_(acc[mt][nt][2])*acc[mt][nt][3];
                out2[(size_t)r0*halfN + j]     = __float2half_rn(v0);
                out2[(size_t)(r0+8)*halfN + j] = __float2half_rn(v1);
            }
        }
    } else {
        #pragma unroll
        for (int mt=0;mt<2;mt++){
            int r0 = bm + warpM*32 + mt*16 + g;
            #pragma unroll
            for (int nt=0;nt<8;nt++){
                int col = bn + warpN*64 + nt*8 + tg*2;
                float2 v0 = make_float2(acc[mt][nt][0], acc[mt][nt][1]);
                float2 v1 = make_float2(acc[mt][nt][2], acc[mt][nt][3]);
                if (addsrc){
                    float2 s0 = *(const float2*)&addsrc[(size_t)r0*N + col];
                    float2 s1 = *(const float2*)&addsrc[(size_t)(r0+8)*N + col];
                    v0.x+=s0.x; v0.y+=s0.y; v1.x+=s1.x; v1.y+=s1.y;
                }
                *(float2*)&C[(size_t)r0*N + col] = v0;
                *(float2*)&C[(size_t)(r0+8)*N + col] = v1;
            }
        }
    }
    #undef ISSUE
}

// ---------------- beta / g small-N projections ----------------
__global__ void beta_g_kernel(const float* __restrict__ x, const float* __restrict__ Wb,
        const float* __restrict__ Wa, const float* __restrict__ A_log,
        const float* __restrict__ dt_bias,
        float* __restrict__ beta, float* __restrict__ g){
    int row = blockIdx.x;
    __shared__ float sx[Dd];
    const float* xr = x + (size_t)row*Dd;
    for (int d=threadIdx.x; d<Dd; d+=128) sx[d]=xr[d];
    __syncthreads();
    int warp = threadIdx.x >> 5, lane = threadIdx.x & 31;
    for (int out = warp; out < 24; out += 4){
        float s = 0.f;
        if (out < 16){
            for (int d=lane; d<Dd; d+=32) s += sx[d]*Wb[d*16 + out];
        } else {
            int c = out - 16;
            for (int d=lane; d<Dd; d+=32) s += sx[d]*Wa[d*8 + c];
        }
        #pragma unroll
        for (int m=16;m;m>>=1) s += __shfl_xor_sync(0xffffffffu, s, m);
        if (lane==0){
            if (out<16) beta[(size_t)row*16 + out] = sigmoidf_(s);
            else {
                int h = out-16;
                float v = s + dt_bias[h];
                float sp = v > 20.f ? v : log1pf(expf(v));
                g[(size_t)row*8 + h] = -expf(A_log[h])*sp;
            }
        }
    }
}

// ---------------- causal conv(K=4)+silu (+opt l2norm/128), per-timestep ----
__global__ void conv_silu_kernel(const float* __restrict__ pre, const float* __restrict__ w,
                                 float* __restrict__ out, int instride, int inoff,
                                 int nch, int do_norm){
    int b = blockIdx.z, t = blockIdx.y;
    int ch = blockIdx.x*128 + threadIdx.x;
    const float* base = pre + (size_t)b*Tt*instride + inoff + ch;
    float acc = 0.f;
    #pragma unroll
    for (int i=0;i<4;i++){
        int tt = t - 3 + i;
        if (tt >= 0)
            acc += base[(size_t)tt*instride] * w[ch*4 + i];
    }
    float s = siluf_(acc);
    if (do_norm){
        float ss = s*s;
        #pragma unroll
        for (int m=16;m;m>>=1) ss += __shfl_xor_sync(0xffffffffu, ss, m);
        __shared__ float sw[4];
        if ((threadIdx.x&31)==0) sw[threadIdx.x>>5] = ss;
        __syncthreads();
        float tot = sw[0]+sw[1]+sw[2]+sw[3];
        s *= rsqrtf(tot + 1e-6f);
    }
    out[((size_t)(b*Tt + t))*nch + ch] = s;
}

// ---------------- recurrent gated delta-product scan ----------------
// 16 DV-chunks (grid.x=16 -> 256 blocks, ~2 CTA/SM latency interleave).
// 256 thr = 16 dkg x 16 vg, 1 v-column per thread. Rank-1 algebra,
// single shfl-reduction phase over 6 variables.
__global__ void __launch_bounds__(256) scan_kernel(
        const float* __restrict__ q, const float* __restrict__ k,
        const float* __restrict__ v, const float* __restrict__ beta,
        const float* __restrict__ g, float* __restrict__ o){
    int vchunk = blockIdx.x, h = blockIdx.y, b = blockIdx.z;
    int tid = threadIdx.x;
    int dkg = tid & 15;
    int vg  = tid >> 4;
    int vbase = vchunk*16;
    __shared__ float sQ[2][144], sK[2][2][144], sV[2][2][16], sS[2][4];
    float S[8];
    #pragma unroll
    for (int i=0;i<8;i++) S[i]=0.f;
    const int chq = h*DK;
    const int kb = dkg*9;

    float rq=0.f, rk=0.f, rv=0.f, rs=0.f;
    {
        size_t bt = (size_t)b*Tt;
        if (tid < 128) rq = q[bt*1024 + chq + tid];
        rk = k[(bt*2 + (tid>>7))*1024 + chq + (tid&127)];
        if (tid < 32) rv = v[(bt*2 + (tid>>4))*2048 + h*DV + vbase + (tid&15)];
        if (tid == 0) rs = g[bt*8 + h];
        else if (tid == 1) rs = beta[bt*16 + h*2 + 0];
        else if (tid == 2) rs = beta[bt*16 + h*2 + 1];
    }

    for (int t=0;t<Tt;t++){
        int p = t & 1;
        if (tid < 128) sQ[p][tid + (tid>>3)] = rq;
        { int dk = tid&127; sK[p][tid>>7][dk + (dk>>3)] = rk; }
        if (tid < 32) sV[p][tid>>4][tid&15] = rv;
        if (tid < 3)  sS[p][tid] = rs;
        __syncthreads();

        if (t+1 < Tt){
            size_t bt = (size_t)b*Tt + t + 1;
            if (tid < 128) rq = q[bt*1024 + chq + tid];
            rk = k[(bt*2 + (tid>>7))*1024 + chq + (tid&127)];
            if (tid < 32) rv = v[(bt*2 + (tid>>4))*2048 + h*DV + vbase + (tid&15)];
            if (tid == 0) rs = g[bt*8 + h];
            else if (tid == 1) rs = beta[bt*16 + h*2 + 0];
            else if (tid == 2) rs = beta[bt*16 + h*2 + 1];
        }

        float kk0[8], kk1[8], qq[8];
        #pragma unroll
        for (int i=0;i<8;i++){
            kk0[i] = sK[p][0][kb+i];
            kk1[i] = sK[p][1][kb+i];
            qq[i]  = sQ[p][kb+i];
        }
        float dec = expf(sS[p][0]);
        float b0 = sS[p][1], b1 = sS[p][2];

        // 6 independent partial dot products
        float p0=0.f,p1=0.f,qt=0.f,skk=0.f,sqk0=0.f,sqk1=0.f;
        #pragma unroll
        for (int i=0;i<8;i++){
            p0  += kk0[i]*S[i];
            p1  += kk1[i]*S[i];
            qt  += qq[i] *S[i];
            skk += kk1[i]*kk0[i];
            sqk0+= qq[i] *kk0[i];
            sqk1+= qq[i] *kk1[i];
        }
        // one shfl-reduction phase (all 6 in parallel, 4 steps over 16 lanes)
        #pragma unroll
        for (int m=1;m<16;m<<=1){
            p0  += __shfl_xor_sync(0xffffffffu, p0,  m);
            p1  += __shfl_xor_sync(0xffffffffu, p1,  m);
            qt  += __shfl_xor_sync(0xffffffffu, qt,  m);
            skk += __shfl_xor_sync(0xffffffffu, skk, m);
            sqk0+= __shfl_xor_sync(0xffffffffu, sqk0,m);
            sqk1+= __shfl_xor_sync(0xffffffffu, sqk1,m);
        }
        // scalar epilogue
        float v0 = sV[p][0][vg], v1 = sV[p][1][vg];
        float d0 = b0*(v0 - dec*p0);
        float d1 = b1*(v1 - (dec*p1 + skk*d0));
        float oo = dec*qt + sqk0*d0 + sqk1*d1;
        #pragma unroll
        for (int i=0;i<8;i++)
            S[i] = dec*S[i] + kk0[i]*d0 + kk1[i]*d1;
        if (dkg == 0)
            o[((size_t)b*Tt + t)*2048 + h*DV + vbase + vg] = oo;
    }
}

// ---------------- o-norm * silu(gate) -> fp16 ----------------
__global__ void ogate_kernel(const float* __restrict__ o, const float* __restrict__ qkvg,
                             const float* __restrict__ onw, __half* __restrict__ o2){
    __shared__ float sh[8];
    int bt = blockIdx.x, h = blockIdx.y, vv = threadIdx.x;
    size_t idx = (size_t)bt*2048 + h*DV + vv;
    float val = o[idx];
    float tot = block_reduce_sum(val*val, sh);
    float scale = rsqrtf(tot/(float)DV + 1e-6f);
    float gt = qkvg[(size_t)bt*NQKVG + 7168 + h*DV + vv];
    float res = val*scale*onw[vv]*siluf_(gt);
    o2[idx] = __float2half_rn(res);
}

// ---------------- launch ----------------
extern "C" void kernel_launch(void* const* d_in, const int* in_sizes, int n_in,
                              void* d_out, int out_size){
    const float* hs         = (const float*)d_in[0];
    const float* attn_nw    = (const float*)d_in[1];
    const float* Wq         = (const float*)d_in[2];
    const float* Wk         = (const float*)d_in[3];
    const float* Wv         = (const float*)d_in[4];
    const float* Wb         = (const float*)d_in[5];
    const float* Wa         = (const float*)d_in[6];
    const float* A_log      = (const float*)d_in[7];
    const float* dt_bias    = (const float*)d_in[8];
    const float* conv_q_w   = (const float*)d_in[9];
    const float* conv_k_w   = (const float*)d_in[10];
    const float* conv_v_w   = (const float*)d_in[11];
    const float* Wg         = (const float*)d_in[12];
    const float* o_norm_w   = (const float*)d_in[13];
    const float* Wo         = (const float*)d_in[14];
    const float* mlp_norm_w = (const float*)d_in[15];
    const float* Wgate      = (const float*)d_in[16];
    const float* Wdown      = (const float*)d_in[17];

    float *x,*qkvg,*qb,*kb,*vb,*betab,*gb,*ob,*hid;
    cudaGetSymbolAddress((void**)&x,    g_x);
    cudaGetSymbolAddress((void**)&qkvg, g_qkvg);
    cudaGetSymbolAddress((void**)&qb,   g_q);
    cudaGetSymbolAddress((void**)&kb,   g_k);
    cudaGetSymbolAddress((void**)&vb,   g_v);
    cudaGetSymbolAddress((void**)&betab,g_beta);
    cudaGetSymbolAddress((void**)&gb,   g_gdec);
    cudaGetSymbolAddress((void**)&ob,   g_o);
    cudaGetSymbolAddress((void**)&hid,  g_hid);

    __half *x2,*y2,*o2,*mlp2,*wqkvg2,*wo2,*wgate2,*wdown2;
    cudaGetSymbolAddress((void**)&x2,    g2_x);
    cudaGetSymbolAddress((void**)&y2,    g2_y);
    cudaGetSymbolAddress((void**)&o2,    g2_o);
    cudaGetSymbolAddress((void**)&mlp2,  g2_mlp);
    cudaGetSymbolAddress((void**)&wqkvg2,g2_Wqkvg);
    cudaGetSymbolAddress((void**)&wo2,   g2_Wo);
    cudaGetSymbolAddress((void**)&wgate2,g2_Wgate);
    cudaGetSymbolAddress((void**)&wdown2,g2_Wdown);

    cudaFuncSetAttribute(mma_gemm, cudaFuncAttributeMaxDynamicSharedMemorySize, GEMM_SMEM);

    // weight conversions into fused/transposed fp16 layouts
    w3_kernel <<<dim3( 32,32),256>>>(Wq,    wqkvg2,                        1024, 1024);
    w3_kernel <<<dim3( 64,32),256>>>(Wk,    wqkvg2 + (size_t)1024*1024,    1024, 2048);
    w3_kernel <<<dim3(128,32),256>>>(Wv,    wqkvg2 + (size_t)3072*1024,    1024, 4096);
    w3_kernel <<<dim3( 64,32),256>>>(Wg,    wqkvg2 + (size_t)7168*1024,    1024, 2048);
    rmsnorm_kernel<<<BT, 256>>>(hs, attn_nw, x, x2, Dd);

    // fused QKVG projection (one GEMM, N=9216, Kp=1024)
    mma_gemm<<<dim3(72,32),256,GEMM_SMEM>>>(x2, wqkvg2, qkvg, nullptr, nullptr, BT, NQKVG, 1024);

    beta_g_kernel<<<BT,128>>>(x, Wb, Wa, A_log, dt_bias, betab, gb);

    // remaining weight conversions (independent; before their consumer GEMMs)
    w3_kernel <<<dim3( 32,64),256>>>(Wo,    wo2,    2048, 1024);
    w3i_kernel<<<dim3(176,32),256>>>(Wgate, wgate2, 1024, 5632);
    w3_kernel <<<dim3( 32,88),256>>>(Wdown, wdown2, 2816, 1024);

    // causal conv + silu (+ l2norm for q,k) over fused buffer, per-timestep
    conv_silu_kernel<<<dim3( 8,Tt,Bb),128>>>(qkvg, conv_q_w, qb, NQKVG,    0, 1024, 1);
    conv_silu_kernel<<<dim3(16,Tt,Bb),128>>>(qkvg, conv_k_w, kb, NQKVG, 1024, 2048, 1);
    conv_silu_kernel<<<dim3(32,Tt,Bb),128>>>(qkvg, conv_v_w, vb, NQKVG, 3072, 4096, 0);

    // gated delta-product recurrence (16 DV-chunks, 2 CTA/SM)
    scan_kernel<<<dim3(16,8,2),256>>>(qb, kb, vb, betab, gb, ob);

    // o = rmsnorm(o)*silu(gate) -> fp16, then Wo + residual (Kp=2048)
    ogate_kernel<<<dim3(BT,Hh),256>>>(ob, qkvg, o_norm_w, o2);
    mma_gemm<<<dim3( 8,32),256,GEMM_SMEM>>>(o2, wo2, hid, hs, nullptr, BT, 1024, 2048);

    // MLP: Wgate GEMM with fused swiglu -> mlp2 (Kp=1024), then Wdown (Kp=2816)
    rmsnorm_kernel<<<BT,256>>>(hid, mlp_norm_w, nullptr, y2, Dd);
    mma_gemm<<<dim3(44,32),256,GEMM_SMEM>>>(y2, wgate2, nullptr, nullptr, mlp2, BT, 5632, 1024);
    mma_gemm<<<dim3( 8,32),256,GEMM_SMEM>>>(mlp2, wdown2, (float*)d_out, hid, nullptr, BT, 1024, 2816);
}

// round 15
// speedup vs baseline: 1.1435x; 1.1435x over previous
#include <cuda_runtime.h>
#include <cuda_fp16.h>
#include <math.h>
#include <stdint.h>

// ---------------- problem constants ----------------
#define Bb 2
#define Tt 2048
#define Dd 1024
#define Hh 8
#define DK 128
#define DV 256
#define NH 2
#define INTER 2816
#define BT (Bb*Tt)              // 4096
#define NQKVG 9216              // 1024 + 2048 + 4096 + 2048

// ---------------- scratch (device globals; no allocation allowed) ----------
__device__ float g_x   [(size_t)BT*Dd];
__device__ float g_qkvg[(size_t)BT*NQKVG];
__device__ float g_q   [(size_t)BT*Hh*DK];
__device__ float g_k   [(size_t)BT*NH*Hh*DK];
__device__ float g_v   [(size_t)BT*NH*Hh*DV];
__device__ float g_beta[(size_t)BT*Hh*NH];
__device__ float g_gdec[(size_t)BT*Hh];
__device__ float g_o   [(size_t)BT*Hh*DV];
__device__ float g_hid [(size_t)BT*Dd];

// fp16 buffers (activations: [M, K]; weights transposed: [N, K])
__device__ __half g2_x    [(size_t)BT*1024];
__device__ __half g2_y    [(size_t)BT*1024];
__device__ __half g2_o    [(size_t)BT*2048];
__device__ __half g2_mlp  [(size_t)BT*2816];
__device__ __half g2_Wqkvg[(size_t)NQKVG*1024];
__device__ __half g2_Wo   [(size_t)1024*2048];
__device__ __half g2_Wgate[(size_t)5632*1024];
__device__ __half g2_Wdown[(size_t)1024*2816];

// ---------------- helpers ----------------
__device__ __forceinline__ uint32_t smem_u32(const void* p){
    uint32_t a;
    asm("{ .reg .u64 t; cvta.to.shared.u64 t, %1; cvt.u32.u64 %0, t; }" : "=r"(a) : "l"(p));
    return a;
}
__device__ __forceinline__ void cp16(uint32_t s, const void* g){
    asm volatile("cp.async.cg.shared.global [%0], [%1], 16;" :: "r"(s), "l"(g) : "memory");
}
__device__ __forceinline__ void ldm4(uint32_t* d, uint32_t addr){
    asm volatile("ldmatrix.sync.aligned.m8n8.x4.shared.b16 {%0,%1,%2,%3}, [%4];"
        : "=r"(d[0]), "=r"(d[1]), "=r"(d[2]), "=r"(d[3]) : "r"(addr));
}
__device__ __forceinline__ void mma16816(float* d, const uint32_t* a, const uint32_t* b){
    asm volatile("mma.sync.aligned.m16n8k16.row.col.f32.f16.f16.f32 "
        "{%0,%1,%2,%3}, {%4,%5,%6,%7}, {%8,%9}, {%0,%1,%2,%3};"
        : "+f"(d[0]), "+f"(d[1]), "+f"(d[2]), "+f"(d[3])
        : "r"(a[0]), "r"(a[1]), "r"(a[2]), "r"(a[3]), "r"(b[0]), "r"(b[1]));
}
__device__ __forceinline__ float sigmoidf_(float x){ return 1.f/(1.f+expf(-x)); }
__device__ __forceinline__ float siluf_(float x){ return x*sigmoidf_(x); }

__device__ __forceinline__ float block_reduce_sum(float v, float* sh){
    int lane = threadIdx.x & 31, warp = threadIdx.x >> 5;
    #pragma unroll
    for (int m=16;m;m>>=1) v += __shfl_xor_sync(0xffffffffu, v, m);
    if (lane==0) sh[warp]=v;
    __syncthreads();
    int nw = (blockDim.x+31)>>5;
    float t = 0.f;
    #pragma unroll
    for (int i=0;i<8;i++) if (i<nw) t += sh[i];
    return t;
}

// ---------------- rmsnorm (optionally emits fp32 and/or fp16) --------------
__global__ void rmsnorm_kernel(const float* __restrict__ in, const float* __restrict__ w,
                               float* __restrict__ out32, __half* __restrict__ out2,
                               int D){
    __shared__ float sh[8];
    int row = blockIdx.x;
    const float* xr = in + (size_t)row*D;
    float ss = 0.f;
    for (int d=threadIdx.x; d<D; d+=blockDim.x){ float v=xr[d]; ss += v*v; }
    float tot = block_reduce_sum(ss, sh);
    float scale = rsqrtf(tot/(float)D + 1e-6f);
    for (int d=threadIdx.x; d<D; d+=blockDim.x){
        float v = xr[d]*scale*w[d];
        if (out32) out32[(size_t)row*D + d] = v;
        if (out2)  out2[(size_t)row*D + d] = __float2half_rn(v);
    }
}

// ---------------- weight [K,N] fp32 -> transposed [N,K] fp16 ---------------
__global__ void w3_kernel(const float* __restrict__ W, __half* __restrict__ B2, int K, int N){
    __shared__ float tile[32][33];
    int n0 = blockIdx.x*32, k0 = blockIdx.y*32;
    int tx = threadIdx.x & 31, ty = threadIdx.x >> 5;
    #pragma unroll
    for (int i=0;i<4;i++)
        tile[ty + i*8][tx] = W[(size_t)(k0 + ty + i*8)*N + n0 + tx];
    __syncthreads();
    #pragma unroll
    for (int i=0;i<4;i++){
        int n = n0 + ty + i*8;
        float v = tile[tx][ty + i*8];
        B2[(size_t)n*K + k0 + tx] = __float2half_rn(v);
    }
}

// -------- Wgate [K,5632] -> interleaved transposed [5632,K] fp16 -----------
__global__ void w3i_kernel(const float* __restrict__ W, __half* __restrict__ B2, int K, int N){
    __shared__ float tile[32][33];
    int n0 = blockIdx.x*32, k0 = blockIdx.y*32;
    int j0 = n0 >> 1, N2 = N >> 1;
    int tx = threadIdx.x & 31, ty = threadIdx.x >> 5;
    int srccol = (tx < 16) ? (j0 + tx) : (N2 + j0 + (tx - 16));
    #pragma unroll
    for (int i=0;i<4;i++)
        tile[ty + i*8][tx] = W[(size_t)(k0 + ty + i*8)*N + srccol];
    __syncthreads();
    #pragma unroll
    for (int i=0;i<4;i++){
        int r = ty + i*8;
        int n = n0 + r;
        float v = tile[tx][(r&1)*16 + (r>>1)];
        B2[(size_t)n*K + k0 + tx] = __float2half_rn(v);
    }
}

// ---------------- fp16 mma.sync GEMM: 128x128, 256 thr, 4 stages, 2 CTA/SM -
#define BKg   32
#define STG   4
#define ROWB  80
#define ATILE (128*ROWB)
#define STILE (2*ATILE)
#define GEMM_SMEM (STG*STILE)

__global__ void __launch_bounds__(256,2) mma_gemm(
        const __half* __restrict__ A, const __half* __restrict__ B,
        float* __restrict__ C, const float* __restrict__ addsrc,
        __half* __restrict__ out2,
        int M, int N, int Kp){
    extern __shared__ char smem[];
    int tid = threadIdx.x;
    int bm = blockIdx.y*128, bn = blockIdx.x*128;
    uint32_t sbase = smem_u32(smem);

    int lane = tid & 31, wid = tid >> 5;
    int warpM = wid >> 1, warpN = wid & 1;
    int g = lane >> 2, tg = lane & 3;
    int q8 = lane >> 3, r8 = lane & 7;

    const char* gAb = (const char*)(A + (size_t)bm*Kp);
    const char* gBb = (const char*)(B + (size_t)bn*Kp);
    int ldr = tid >> 2, ldc = tid & 3;
    const int nch = Kp / BKg;

    #define ISSUE(chunk, slot) do { \
        uint32_t sA_ = sbase + (slot)*STILE; \
        uint32_t sB_ = sA_ + ATILE; \
        size_t kof = (size_t)(chunk)*BKg*2; \
        _Pragma("unroll") \
        for (int i_=0;i_<2;i_++){ \
            int row_ = ldr + i_*64; \
            cp16(sA_ + row_*ROWB + ldc*16, gAb + (size_t)row_*Kp*2 + kof + ldc*16); \
            cp16(sB_ + row_*ROWB + ldc*16, gBb + (size_t)row_*Kp*2 + kof + ldc*16); \
        } \
        asm volatile("cp.async.commit_group;" ::: "memory"); \
    } while(0)

    float acc[2][8][4];
    #pragma unroll
    for (int mt=0;mt<2;mt++)
        #pragma unroll
        for (int nt=0;nt<8;nt++)
            #pragma unroll
            for (int i=0;i<4;i++) acc[mt][nt][i]=0.f;

    ISSUE(0,0);
    ISSUE(1,1);
    ISSUE(2,2);

    for (int c=0; c<nch; c++){
        asm volatile("cp.async.wait_group 2;" ::: "memory");
        __syncthreads();
        if (c+3 < nch) ISSUE(c+3, (c+3)&3);
        else asm volatile("cp.async.commit_group;" ::: "memory");

        uint32_t sA = sbase + (c&3)*STILE;
        uint32_t sB = sA + ATILE;
        #pragma unroll
        for (int ks=0; ks<2; ks++){
            uint32_t a[2][4], b[4][4];
            #pragma unroll
            for (int mt=0;mt<2;mt++){
                uint32_t addr = sA + (uint32_t)((warpM*32 + mt*16 + (q8&1)*8 + r8)*ROWB
                                + ks*32 + (q8>>1)*16);
                ldm4(a[mt], addr);
            }
            #pragma unroll
            for (int pr=0;pr<4;pr++){
                uint32_t addr = sB + (uint32_t)((warpN*64 + pr*16 + (q8>>1)*8 + r8)*ROWB
                                + ks*32 + (q8&1)*16);
                ldm4(b[pr], addr);
            }
            #pragma unroll
            for (int mt=0;mt<2;mt++)
                #pragma unroll
                for (int nt=0;nt<8;nt++)
                    mma16816(acc[mt][nt], a[mt], &b[nt>>1][(nt&1)*2]);
        }
    }

    if (out2){
        int halfN = N >> 1;                     // = INTER
        #pragma unroll
        for (int mt=0;mt<2;mt++){
            int r0 = bm + warpM*32 + mt*16 + g;
            #pragma unroll
            for (int nt=0;nt<8;nt++){
                int col = bn + warpN*64 + nt*8 + tg*2;
                int j = col >> 1;
                float v0 = siluf_(acc[mt][nt][0])*acc[mt][nt][1];
                float v1 = siluf_(acc[mt][nt][2])*acc[mt][nt][3];
                out2[(size_t)r0*halfN + j]     = __float2half_rn(v0);
                out2[(size_t)(r0+8)*halfN + j] = __float2half_rn(v1);
            }
        }
    } else {
        #pragma unroll
        for (int mt=0;mt<2;mt++){
            int r0 = bm + warpM*32 + mt*16 + g;
            #pragma unroll
            for (int nt=0;nt<8;nt++){
                int col = bn + warpN*64 + nt*8 + tg*2;
                float2 v0 = make_float2(acc[mt][nt][0], acc[mt][nt][1]);
                float2 v1 = make_float2(acc[mt][nt][2], acc[mt][nt][3]);
                if (addsrc){
                    float2 s0 = *(const float2*)&addsrc[(size_t)r0*N + col];
                    float2 s1 = *(const float2*)&addsrc[(size_t)(r0+8)*N + col];
                    v0.x+=s0.x; v0.y+=s0.y; v1.x+=s1.x; v1.y+=s1.y;
                }
                *(float2*)&C[(size_t)r0*N + col] = v0;
                *(float2*)&C[(size_t)(r0+8)*N + col] = v1;
            }
        }
    }
    #undef ISSUE
}

// ---------------- beta / g small-N projections ----------------
__global__ void beta_g_kernel(const float* __restrict__ x, const float* __restrict__ Wb,
        const float* __restrict__ Wa, const float* __restrict__ A_log,
        const float* __restrict__ dt_bias,
        float* __restrict__ beta, float* __restrict__ g){
    int row = blockIdx.x;
    __shared__ float sx[Dd];
    const float* xr = x + (size_t)row*Dd;
    for (int d=threadIdx.x; d<Dd; d+=128) sx[d]=xr[d];
    __syncthreads();
    int warp = threadIdx.x >> 5, lane = threadIdx.x & 31;
    for (int out = warp; out < 24; out += 4){
        float s = 0.f;
        if (out < 16){
            for (int d=lane; d<Dd; d+=32) s += sx[d]*Wb[d*16 + out];
        } else {
            int c = out - 16;
            for (int d=lane; d<Dd; d+=32) s += sx[d]*Wa[d*8 + c];
        }
        #pragma unroll
        for (int m=16;m;m>>=1) s += __shfl_xor_sync(0xffffffffu, s, m);
        if (lane==0){
            if (out<16) beta[(size_t)row*16 + out] = sigmoidf_(s);
            else {
                int h = out-16;
                float v = s + dt_bias[h];
                float sp = v > 20.f ? v : log1pf(expf(v));
                g[(size_t)row*8 + h] = -expf(A_log[h])*sp;
            }
        }
    }
}

// ------- causal conv(K=4)+silu (+opt l2norm/128), 4 timesteps/block --------
__global__ void __launch_bounds__(128) conv_silu4_kernel(
        const float* __restrict__ pre, const float* __restrict__ w,
        float* __restrict__ out, int instride, int inoff,
        int nch, int do_norm){
    int b = blockIdx.z;
    int t0 = blockIdx.y*4;
    int ch = blockIdx.x*128 + threadIdx.x;
    float w0=w[ch*4+0], w1=w[ch*4+1], w2=w[ch*4+2], w3=w[ch*4+3];
    const float* base = pre + (size_t)b*Tt*instride + inoff + ch;
    float x0 = (t0>=3) ? base[(size_t)(t0-3)*instride] : 0.f;
    float x1 = (t0>=2) ? base[(size_t)(t0-2)*instride] : 0.f;
    float x2 = (t0>=1) ? base[(size_t)(t0-1)*instride] : 0.f;
    __shared__ float sw[4];
    #pragma unroll
    for (int i=0;i<4;i++){
        int t = t0 + i;
        float x3v = base[(size_t)t*instride];
        float acc = w0*x0 + w1*x1 + w2*x2 + w3*x3v;
        float s = siluf_(acc);
        if (do_norm){
            float ss = s*s;
            #pragma unroll
            for (int m=16;m;m>>=1) ss += __shfl_xor_sync(0xffffffffu, ss, m);
            if ((threadIdx.x&31)==0) sw[threadIdx.x>>5] = ss;
            __syncthreads();
            float tot = sw[0]+sw[1]+sw[2]+sw[3];
            s *= rsqrtf(tot + 1e-6f);
            __syncthreads();
        }
        out[((size_t)(b*Tt + t))*nch + ch] = s;
        x0=x1; x1=x2; x2=x3v;
    }
}

// ---------------- recurrent gated delta-product scan (R13: 8 DV-chunks) ----
// rank-1 algebra, single shfl-reduction phase over 9 variables
__global__ void __launch_bounds__(256) scan_kernel(
        const float* __restrict__ q, const float* __restrict__ k,
        const float* __restrict__ v, const float* __restrict__ beta,
        const float* __restrict__ g, float* __restrict__ o){
    int vchunk = blockIdx.x, h = blockIdx.y, b = blockIdx.z;
    int tid = threadIdx.x;
    int dkg = tid & 15;
    int vg  = tid >> 4;
    int vbase = vchunk*32;
    __shared__ float sQ[2][144], sK[2][2][144], sV[2][2][32], sS[2][4];
    float S[8][2];
    #pragma unroll
    for (int i=0;i<8;i++){ S[i][0]=0.f; S[i][1]=0.f; }
    const int chq = h*DK;
    const int kb = dkg*9;

    float rq=0.f, rk=0.f, rv=0.f, rs=0.f;
    {
        size_t bt = (size_t)b*Tt;
        if (tid < 128) rq = q[bt*1024 + chq + tid];
        rk = k[(bt*2 + (tid>>7))*1024 + chq + (tid&127)];
        if (tid < 64) rv = v[(bt*2 + (tid>>5))*2048 + h*DV + vbase + (tid&31)];
        if (tid == 0) rs = g[bt*8 + h];
        else if (tid == 1) rs = beta[bt*16 + h*2 + 0];
        else if (tid == 2) rs = beta[bt*16 + h*2 + 1];
    }

    for (int t=0;t<Tt;t++){
        int p = t & 1;
        if (tid < 128) sQ[p][tid + (tid>>3)] = rq;
        { int dk = tid&127; sK[p][tid>>7][dk + (dk>>3)] = rk; }
        if (tid < 64) sV[p][tid>>5][tid&31] = rv;
        if (tid < 3)  sS[p][tid] = rs;
        __syncthreads();

        if (t+1 < Tt){
            size_t bt = (size_t)b*Tt + t + 1;
            if (tid < 128) rq = q[bt*1024 + chq + tid];
            rk = k[(bt*2 + (tid>>7))*1024 + chq + (tid&127)];
            if (tid < 64) rv = v[(bt*2 + (tid>>5))*2048 + h*DV + vbase + (tid&31)];
            if (tid == 0) rs = g[bt*8 + h];
            else if (tid == 1) rs = beta[bt*16 + h*2 + 0];
            else if (tid == 2) rs = beta[bt*16 + h*2 + 1];
        }

        float kk0[8], kk1[8], qq[8];
        #pragma unroll
        for (int i=0;i<8;i++){
            kk0[i] = sK[p][0][kb+i];
            kk1[i] = sK[p][1][kb+i];
            qq[i]  = sQ[p][kb+i];
        }
        float dec = expf(sS[p][0]);
        float b0 = sS[p][1], b1 = sS[p][2];

        float p00=0.f,p01=0.f,p10=0.f,p11=0.f,q0=0.f,q1=0.f,skk=0.f,sqk0=0.f,sqk1=0.f;
        #pragma unroll
        for (int i=0;i<8;i++){
            p00 += kk0[i]*S[i][0]; p01 += kk0[i]*S[i][1];
            p10 += kk1[i]*S[i][0]; p11 += kk1[i]*S[i][1];
            q0  += qq[i] *S[i][0]; q1  += qq[i] *S[i][1];
            skk += kk1[i]*kk0[i];  sqk0 += qq[i]*kk0[i]; sqk1 += qq[i]*kk1[i];
        }
        #pragma unroll
        for (int m=1;m<16;m<<=1){
            p00 += __shfl_xor_sync(0xffffffffu, p00, m);
            p01 += __shfl_xor_sync(0xffffffffu, p01, m);
            p10 += __shfl_xor_sync(0xffffffffu, p10, m);
            p11 += __shfl_xor_sync(0xffffffffu, p11, m);
            q0  += __shfl_xor_sync(0xffffffffu, q0,  m);
            q1  += __shfl_xor_sync(0xffffffffu, q1,  m);
            skk += __shfl_xor_sync(0xffffffffu, skk, m);
            sqk0+= __shfl_xor_sync(0xffffffffu, sqk0,m);
            sqk1+= __shfl_xor_sync(0xffffffffu, sqk1,m);
        }
        float v00 = sV[p][0][vg*2+0], v01 = sV[p][0][vg*2+1];
        float v10 = sV[p][1][vg*2+0], v11 = sV[p][1][vg*2+1];
        float d00 = b0*(v00 - dec*p00);
        float d01 = b0*(v01 - dec*p01);
        float d10 = b1*(v10 - (dec*p10 + skk*d00));
        float d11 = b1*(v11 - (dec*p11 + skk*d01));
        float o0 = dec*q0 + sqk0*d00 + sqk1*d10;
        float o1 = dec*q1 + sqk0*d01 + sqk1*d11;
        #pragma unroll
        for (int i=0;i<8;i++){
            S[i][0] = dec*S[i][0] + kk0[i]*d00 + kk1[i]*d10;
            S[i][1] = dec*S[i][1] + kk0[i]*d01 + kk1[i]*d11;
        }
        if (dkg == 0){
            size_t ob = ((size_t)b*Tt + t)*2048 + h*DV + vbase + vg*2;
            o[ob]   = o0;
            o[ob+1] = o1;
        }
    }
}

// ---------------- o-norm * silu(gate) -> fp16 ----------------
__global__ void ogate_kernel(const float* __restrict__ o, const float* __restrict__ qkvg,
                             const float* __restrict__ onw, __half* __restrict__ o2){
    __shared__ float sh[8];
    int bt = blockIdx.x, h = blockIdx.y, vv = threadIdx.x;
    size_t idx = (size_t)bt*2048 + h*DV + vv;
    float val = o[idx];
    float tot = block_reduce_sum(val*val, sh);
    float scale = rsqrtf(tot/(float)DV + 1e-6f);
    float gt = qkvg[(size_t)bt*NQKVG + 7168 + h*DV + vv];
    float res = val*scale*onw[vv]*siluf_(gt);
    o2[idx] = __float2half_rn(res);
}

// ---------------- launch ----------------
extern "C" void kernel_launch(void* const* d_in, const int* in_sizes, int n_in,
                              void* d_out, int out_size){
    const float* hs         = (const float*)d_in[0];
    const float* attn_nw    = (const float*)d_in[1];
    const float* Wq         = (const float*)d_in[2];
    const float* Wk         = (const float*)d_in[3];
    const float* Wv         = (const float*)d_in[4];
    const float* Wb         = (const float*)d_in[5];
    const float* Wa         = (const float*)d_in[6];
    const float* A_log      = (const float*)d_in[7];
    const float* dt_bias    = (const float*)d_in[8];
    const float* conv_q_w   = (const float*)d_in[9];
    const float* conv_k_w   = (const float*)d_in[10];
    const float* conv_v_w   = (const float*)d_in[11];
    const float* Wg         = (const float*)d_in[12];
    const float* o_norm_w   = (const float*)d_in[13];
    const float* Wo         = (const float*)d_in[14];
    const float* mlp_norm_w = (const float*)d_in[15];
    const float* Wgate      = (const float*)d_in[16];
    const float* Wdown      = (const float*)d_in[17];

    float *x,*qkvg,*qb,*kb,*vb,*betab,*gb,*ob,*hid;
    cudaGetSymbolAddress((void**)&x,    g_x);
    cudaGetSymbolAddress((void**)&qkvg, g_qkvg);
    cudaGetSymbolAddress((void**)&qb,   g_q);
    cudaGetSymbolAddress((void**)&kb,   g_k);
    cudaGetSymbolAddress((void**)&vb,   g_v);
    cudaGetSymbolAddress((void**)&betab,g_beta);
    cudaGetSymbolAddress((void**)&gb,   g_gdec);
    cudaGetSymbolAddress((void**)&ob,   g_o);
    cudaGetSymbolAddress((void**)&hid,  g_hid);

    __half *x2,*y2,*o2,*mlp2,*wqkvg2,*wo2,*wgate2,*wdown2;
    cudaGetSymbolAddress((void**)&x2,    g2_x);
    cudaGetSymbolAddress((void**)&y2,    g2_y);
    cudaGetSymbolAddress((void**)&o2,    g2_o);
    cudaGetSymbolAddress((void**)&mlp2,  g2_mlp);
    cudaGetSymbolAddress((void**)&wqkvg2,g2_Wqkvg);
    cudaGetSymbolAddress((void**)&wo2,   g2_Wo);
    cudaGetSymbolAddress((void**)&wgate2,g2_Wgate);
    cudaGetSymbolAddress((void**)&wdown2,g2_Wdown);

    cudaFuncSetAttribute(mma_gemm, cudaFuncAttributeMaxDynamicSharedMemorySize, GEMM_SMEM);

    // weight conversions into fused/transposed fp16 layouts
    w3_kernel <<<dim3( 32,32),256>>>(Wq,    wqkvg2,                        1024, 1024);
    w3_kernel <<<dim3( 64,32),256>>>(Wk,    wqkvg2 + (size_t)1024*1024,    1024, 2048);
    w3_kernel <<<dim3(128,32),256>>>(Wv,    wqkvg2 + (size_t)3072*1024,    1024, 4096);
    w3_kernel <<<dim3( 64,32),256>>>(Wg,    wqkvg2 + (size_t)7168*1024,    1024, 2048);
    rmsnorm_kernel<<<BT, 256>>>(hs, attn_nw, x, x2, Dd);

    // fused QKVG projection (one GEMM, N=9216, Kp=1024)
    mma_gemm<<<dim3(72,32),256,GEMM_SMEM>>>(x2, wqkvg2, qkvg, nullptr, nullptr, BT, NQKVG, 1024);

    beta_g_kernel<<<BT,128>>>(x, Wb, Wa, A_log, dt_bias, betab, gb);

    // remaining weight conversions (independent; before their consumer GEMMs)
    w3_kernel <<<dim3( 32,64),256>>>(Wo,    wo2,    2048, 1024);
    w3i_kernel<<<dim3(176,32),256>>>(Wgate, wgate2, 1024, 5632);
    w3_kernel <<<dim3( 32,88),256>>>(Wdown, wdown2, 2816, 1024);

    // causal conv + silu (+ l2norm for q,k), 4 timesteps per block
    conv_silu4_kernel<<<dim3( 8,Tt/4,Bb),128>>>(qkvg, conv_q_w, qb, NQKVG,    0, 1024, 1);
    conv_silu4_kernel<<<dim3(16,Tt/4,Bb),128>>>(qkvg, conv_k_w, kb, NQKVG, 1024, 2048, 1);
    conv_silu4_kernel<<<dim3(32,Tt/4,Bb),128>>>(qkvg, conv_v_w, vb, NQKVG, 3072, 4096, 0);

    // gated delta-product recurrence (8 DV-chunks, R13 config)
    scan_kernel<<<dim3(8,8,2),256>>>(qb, kb, vb, betab, gb, ob);

    // o = rmsnorm(o)*silu(gate) -> fp16, then Wo + residual (Kp=2048)
    ogate_kernel<<<dim3(BT,Hh),256>>>(ob, qkvg, o_norm_w, o2);
    mma_gemm<<<dim3( 8,32),256,GEMM_SMEM>>>(o2, wo2, hid, hs, nullptr, BT, 1024, 2048);

    // MLP: Wgate GEMM with fused swiglu -> mlp2 (Kp=1024), then Wdown (Kp=2816)
    rmsnorm_kernel<<<BT,256>>>(hid, mlp_norm_w, nullptr, y2, Dd);
    mma_gemm<<<dim3(44,32),256,GEMM_SMEM>>>(y2, wgate2, nullptr, nullptr, mlp2, BT, 5632, 1024);
    mma_gemm<<<dim3( 8,32),256,GEMM_SMEM>>>(mlp2, wdown2, (float*)d_out, hid, nullptr, BT, 1024, 2816);
}

// round 16
// speedup vs baseline: 1.2321x; 1.0775x over previous
#include <cuda_runtime.h>
#include <cuda_fp16.h>
#include <math.h>
#include <stdint.h>

// ---------------- problem constants ----------------
#define Bb 2
#define Tt 2048
#define Dd 1024
#define Hh 8
#define DK 128
#define DV 256
#define NH 2
#define INTER 2816
#define BT (Bb*Tt)              // 4096
#define NQ2 9344                // 1024 + 2048 + 4096 + 2048 + 24(beta,g) + pad -> 73*128

// ---------------- scratch (device globals; no allocation allowed) ----------
__device__ float g_qkvg[(size_t)BT*NQ2];
__device__ float g_q   [(size_t)BT*Hh*DK];
__device__ float g_k   [(size_t)BT*NH*Hh*DK];
__device__ float g_v   [(size_t)BT*NH*Hh*DV];
__device__ float g_beta[(size_t)BT*Hh*NH];
__device__ float g_gdec[(size_t)BT*Hh];
__device__ float g_o   [(size_t)BT*Hh*DV];
__device__ float g_hid [(size_t)BT*Dd];

// fp16 buffers (activations: [M, K]; weights transposed: [N, K])
__device__ __half g2_x    [(size_t)BT*1024];
__device__ __half g2_y    [(size_t)BT*1024];
__device__ __half g2_o    [(size_t)BT*2048];
__device__ __half g2_mlp  [(size_t)BT*2816];
__device__ __half g2_Wqkvg[(size_t)NQ2*1024];    // rows 9240..9343 stay zero
__device__ __half g2_Wo   [(size_t)1024*2048];
__device__ __half g2_Wgate[(size_t)5632*1024];
__device__ __half g2_Wdown[(size_t)1024*2816];

// ---------------- helpers ----------------
__device__ __forceinline__ uint32_t smem_u32(const void* p){
    uint32_t a;
    asm("{ .reg .u64 t; cvta.to.shared.u64 t, %1; cvt.u32.u64 %0, t; }" : "=r"(a) : "l"(p));
    return a;
}
__device__ __forceinline__ void cp16(uint32_t s, const void* g){
    asm volatile("cp.async.cg.shared.global [%0], [%1], 16;" :: "r"(s), "l"(g) : "memory");
}
__device__ __forceinline__ void ldm4(uint32_t* d, uint32_t addr){
    asm volatile("ldmatrix.sync.aligned.m8n8.x4.shared.b16 {%0,%1,%2,%3}, [%4];"
        : "=r"(d[0]), "=r"(d[1]), "=r"(d[2]), "=r"(d[3]) : "r"(addr));
}
__device__ __forceinline__ void mma16816(float* d, const uint32_t* a, const uint32_t* b){
    asm volatile("mma.sync.aligned.m16n8k16.row.col.f32.f16.f16.f32 "
        "{%0,%1,%2,%3}, {%4,%5,%6,%7}, {%8,%9}, {%0,%1,%2,%3};"
        : "+f"(d[0]), "+f"(d[1]), "+f"(d[2]), "+f"(d[3])
        : "r"(a[0]), "r"(a[1]), "r"(a[2]), "r"(a[3]), "r"(b[0]), "r"(b[1]));
}
__device__ __forceinline__ float sigmoidf_(float x){ return 1.f/(1.f+expf(-x)); }
__device__ __forceinline__ float siluf_(float x){ return x*sigmoidf_(x); }

__device__ __forceinline__ float block_reduce_sum(float v, float* sh){
    int lane = threadIdx.x & 31, warp = threadIdx.x >> 5;
    #pragma unroll
    for (int m=16;m;m>>=1) v += __shfl_xor_sync(0xffffffffu, v, m);
    if (lane==0) sh[warp]=v;
    __syncthreads();
    int nw = (blockDim.x+31)>>5;
    float t = 0.f;
    #pragma unroll
    for (int i=0;i<8;i++) if (i<nw) t += sh[i];
    return t;
}

// ---------------- rmsnorm -> fp16 ----------------
__global__ void rmsnorm_kernel(const float* __restrict__ in, const float* __restrict__ w,
                               __half* __restrict__ out2, int D){
    __shared__ float sh[8];
    int row = blockIdx.x;
    const float* xr = in + (size_t)row*D;
    float ss = 0.f;
    for (int d=threadIdx.x; d<D; d+=blockDim.x){ float v=xr[d]; ss += v*v; }
    float tot = block_reduce_sum(ss, sh);
    float scale = rsqrtf(tot/(float)D + 1e-6f);
    for (int d=threadIdx.x; d<D; d+=blockDim.x){
        float v = xr[d]*scale*w[d];
        out2[(size_t)row*D + d] = __float2half_rn(v);
    }
}

// ---------------- weight [K,N] fp32 -> transposed [N,K] fp16 ---------------
__global__ void w3_kernel(const float* __restrict__ W, __half* __restrict__ B2, int K, int N){
    __shared__ float tile[32][33];
    int n0 = blockIdx.x*32, k0 = blockIdx.y*32;
    int tx = threadIdx.x & 31, ty = threadIdx.x >> 5;
    #pragma unroll
    for (int i=0;i<4;i++)
        tile[ty + i*8][tx] = W[(size_t)(k0 + ty + i*8)*N + n0 + tx];
    __syncthreads();
    #pragma unroll
    for (int i=0;i<4;i++){
        int n = n0 + ty + i*8;
        float v = tile[tx][ty + i*8];
        B2[(size_t)n*K + k0 + tx] = __float2half_rn(v);
    }
}

// -------- Wb [D,16] + Wa [D,8] -> rows 9216..9239 of fused weight ----------
__global__ void w3b_kernel(const float* __restrict__ Wb, const float* __restrict__ Wa,
                           __half* __restrict__ B2){
    int n = blockIdx.x;     // 0..23
    for (int d = threadIdx.x; d < 1024; d += 256){
        float v = (n < 16) ? Wb[d*16 + n] : Wa[d*8 + (n-16)];
        B2[(size_t)(9216 + n)*1024 + d] = __float2half_rn(v);
    }
}

// -------- Wgate [K,5632] -> interleaved transposed [5632,K] fp16 -----------
__global__ void w3i_kernel(const float* __restrict__ W, __half* __restrict__ B2, int K, int N){
    __shared__ float tile[32][33];
    int n0 = blockIdx.x*32, k0 = blockIdx.y*32;
    int j0 = n0 >> 1, N2 = N >> 1;
    int tx = threadIdx.x & 31, ty = threadIdx.x >> 5;
    int srccol = (tx < 16) ? (j0 + tx) : (N2 + j0 + (tx - 16));
    #pragma unroll
    for (int i=0;i<4;i++)
        tile[ty + i*8][tx] = W[(size_t)(k0 + ty + i*8)*N + srccol];
    __syncthreads();
    #pragma unroll
    for (int i=0;i<4;i++){
        int r = ty + i*8;
        int n = n0 + r;
        float v = tile[tx][(r&1)*16 + (r>>1)];
        B2[(size_t)n*K + k0 + tx] = __float2half_rn(v);
    }
}

// ---------------- fp16 mma.sync GEMM: 128x128, 256 thr, 4 stages, 2 CTA/SM -
#define BKg   32
#define STG   4
#define ROWB  80
#define ATILE (128*ROWB)
#define STILE (2*ATILE)
#define GEMM_SMEM (STG*STILE)

__global__ void __launch_bounds__(256,2) mma_gemm(
        const __half* __restrict__ A, const __half* __restrict__ B,
        float* __restrict__ C, const float* __restrict__ addsrc,
        __half* __restrict__ out2,
        int M, int N, int Kp){
    extern __shared__ char smem[];
    int tid = threadIdx.x;
    int bm = blockIdx.y*128, bn = blockIdx.x*128;
    uint32_t sbase = smem_u32(smem);

    int lane = tid & 31, wid = tid >> 5;
    int warpM = wid >> 1, warpN = wid & 1;
    int g = lane >> 2, tg = lane & 3;
    int q8 = lane >> 3, r8 = lane & 7;

    const char* gAb = (const char*)(A + (size_t)bm*Kp);
    const char* gBb = (const char*)(B + (size_t)bn*Kp);
    int ldr = tid >> 2, ldc = tid & 3;
    const int nch = Kp / BKg;

    #define ISSUE(chunk, slot) do { \
        uint32_t sA_ = sbase + (slot)*STILE; \
        uint32_t sB_ = sA_ + ATILE; \
        size_t kof = (size_t)(chunk)*BKg*2; \
        _Pragma("unroll") \
        for (int i_=0;i_<2;i_++){ \
            int row_ = ldr + i_*64; \
            cp16(sA_ + row_*ROWB + ldc*16, gAb + (size_t)row_*Kp*2 + kof + ldc*16); \
            cp16(sB_ + row_*ROWB + ldc*16, gBb + (size_t)row_*Kp*2 + kof + ldc*16); \
        } \
        asm volatile("cp.async.commit_group;" ::: "memory"); \
    } while(0)

    float acc[2][8][4];
    #pragma unroll
    for (int mt=0;mt<2;mt++)
        #pragma unroll
        for (int nt=0;nt<8;nt++)
            #pragma unroll
            for (int i=0;i<4;i++) acc[mt][nt][i]=0.f;

    ISSUE(0,0);
    ISSUE(1,1);
    ISSUE(2,2);

    for (int c=0; c<nch; c++){
        asm volatile("cp.async.wait_group 2;" ::: "memory");
        __syncthreads();
        if (c+3 < nch) ISSUE(c+3, (c+3)&3);
        else asm volatile("cp.async.commit_group;" ::: "memory");

        uint32_t sA = sbase + (c&3)*STILE;
        uint32_t sB = sA + ATILE;
        #pragma unroll
        for (int ks=0; ks<2; ks++){
            uint32_t a[2][4], b[4][4];
            #pragma unroll
            for (int mt=0;mt<2;mt++){
                uint32_t addr = sA + (uint32_t)((warpM*32 + mt*16 + (q8&1)*8 + r8)*ROWB
                                + ks*32 + (q8>>1)*16);
                ldm4(a[mt], addr);
            }
            #pragma unroll
            for (int pr=0;pr<4;pr++){
                uint32_t addr = sB + (uint32_t)((warpN*64 + pr*16 + (q8>>1)*8 + r8)*ROWB
                                + ks*32 + (q8&1)*16);
                ldm4(b[pr], addr);
            }
            #pragma unroll
            for (int mt=0;mt<2;mt++)
                #pragma unroll
                for (int nt=0;nt<8;nt++)
                    mma16816(acc[mt][nt], a[mt], &b[nt>>1][(nt&1)*2]);
        }
    }

    if (out2){
        int halfN = N >> 1;                     // = INTER
        #pragma unroll
        for (int mt=0;mt<2;mt++){
            int r0 = bm + warpM*32 + mt*16 + g;
            #pragma unroll
            for (int nt=0;nt<8;nt++){
                int col = bn + warpN*64 + nt*8 + tg*2;
                int j = col >> 1;
                float v0 = siluf_(acc[mt][nt][0])*acc[mt][nt][1];
                float v1 = siluf_(acc[mt][nt][2])*acc[mt][nt][3];
                out2[(size_t)r0*halfN + j]     = __float2half_rn(v0);
                out2[(size_t)(r0+8)*halfN + j] = __float2half_rn(v1);
            }
        }
    } else {
        #pragma unroll
        for (int mt=0;mt<2;mt++){
            int r0 = bm + warpM*32 + mt*16 + g;
            #pragma unroll
            for (int nt=0;nt<8;nt++){
                int col = bn + warpN*64 + nt*8 + tg*2;
                float2 v0 = make_float2(acc[mt][nt][0], acc[mt][nt][1]);
                float2 v1 = make_float2(acc[mt][nt][2], acc[mt][nt][3]);
                if (addsrc){
                    float2 s0 = *(const float2*)&addsrc[(size_t)r0*N + col];
                    float2 s1 = *(const float2*)&addsrc[(size_t)(r0+8)*N + col];
                    v0.x+=s0.x; v0.y+=s0.y; v1.x+=s1.x; v1.y+=s1.y;
                }
                *(float2*)&C[(size_t)r0*N + col] = v0;
                *(float2*)&C[(size_t)(r0+8)*N + col] = v1;
            }
        }
    }
    #undef ISSUE
}

// --------- beta/g epilogue from fused GEMM cols 9216..9239 -----------------
__global__ void betag_post(const float* __restrict__ qkvg,
                           const float* __restrict__ A_log, const float* __restrict__ dt_bias,
                           float* __restrict__ beta, float* __restrict__ g){
    int row = blockIdx.x;
    int lane = threadIdx.x;
    if (lane < 24){
        float s = qkvg[(size_t)row*NQ2 + 9216 + lane];
        if (lane < 16){
            beta[(size_t)row*16 + lane] = sigmoidf_(s);
        } else {
            int h = lane - 16;
            float v = s + dt_bias[h];
            float sp = v > 20.f ? v : log1pf(expf(v));
            g[(size_t)row*8 + h] = -expf(A_log[h])*sp;
        }
    }
}

// ------- causal conv(K=4)+silu (+opt l2norm/128), 4 timesteps/block --------
__global__ void __launch_bounds__(128) conv_silu4_kernel(
        const float* __restrict__ pre, const float* __restrict__ w,
        float* __restrict__ out, int instride, int inoff,
        int nch, int do_norm){
    int b = blockIdx.z;
    int t0 = blockIdx.y*4;
    int ch = blockIdx.x*128 + threadIdx.x;
    float w0=w[ch*4+0], w1=w[ch*4+1], w2=w[ch*4+2], w3=w[ch*4+3];
    const float* base = pre + (size_t)b*Tt*instride + inoff + ch;
    float x0 = (t0>=3) ? base[(size_t)(t0-3)*instride] : 0.f;
    float x1 = (t0>=2) ? base[(size_t)(t0-2)*instride] : 0.f;
    float x2 = (t0>=1) ? base[(size_t)(t0-1)*instride] : 0.f;
    __shared__ float sw[4];
    #pragma unroll
    for (int i=0;i<4;i++){
        int t = t0 + i;
        float x3v = base[(size_t)t*instride];
        float acc = w0*x0 + w1*x1 + w2*x2 + w3*x3v;
        float s = siluf_(acc);
        if (do_norm){
            float ss = s*s;
            #pragma unroll
            for (int m=16;m;m>>=1) ss += __shfl_xor_sync(0xffffffffu, ss, m);
            if ((threadIdx.x&31)==0) sw[threadIdx.x>>5] = ss;
            __syncthreads();
            float tot = sw[0]+sw[1]+sw[2]+sw[3];
            s *= rsqrtf(tot + 1e-6f);
            __syncthreads();
        }
        out[((size_t)(b*Tt + t))*nch + ch] = s;
        x0=x1; x1=x2; x2=x3v;
    }
}

// ---------------- recurrent gated delta-product scan (8 DV-chunks) ---------
__global__ void __launch_bounds__(256) scan_kernel(
        const float* __restrict__ q, const float* __restrict__ k,
        const float* __restrict__ v, const float* __restrict__ beta,
        const float* __restrict__ g, float* __restrict__ o){
    int vchunk = blockIdx.x, h = blockIdx.y, b = blockIdx.z;
    int tid = threadIdx.x;
    int dkg = tid & 15;
    int vg  = tid >> 4;
    int vbase = vchunk*32;
    __shared__ float sQ[2][144], sK[2][2][144], sV[2][2][32], sS[2][4];
    float S[8][2];
    #pragma unroll
    for (int i=0;i<8;i++){ S[i][0]=0.f; S[i][1]=0.f; }
    const int chq = h*DK;
    const int kb = dkg*9;

    float rq=0.f, rk=0.f, rv=0.f, rs=0.f;
    {
        size_t bt = (size_t)b*Tt;
        if (tid < 128) rq = q[bt*1024 + chq + tid];
        rk = k[(bt*2 + (tid>>7))*1024 + chq + (tid&127)];
        if (tid < 64) rv = v[(bt*2 + (tid>>5))*2048 + h*DV + vbase + (tid&31)];
        if (tid == 0) rs = g[bt*8 + h];
        else if (tid == 1) rs = beta[bt*16 + h*2 + 0];
        else if (tid == 2) rs = beta[bt*16 + h*2 + 1];
    }

    for (int t=0;t<Tt;t++){
        int p = t & 1;
        if (tid < 128) sQ[p][tid + (tid>>3)] = rq;
        { int dk = tid&127; sK[p][tid>>7][dk + (dk>>3)] = rk; }
        if (tid < 64) sV[p][tid>>5][tid&31] = rv;
        if (tid < 3)  sS[p][tid] = rs;
        __syncthreads();

        if (t+1 < Tt){
            size_t bt = (size_t)b*Tt + t + 1;
            if (tid < 128) rq = q[bt*1024 + chq + tid];
            rk = k[(bt*2 + (tid>>7))*1024 + chq + (tid&127)];
            if (tid < 64) rv = v[(bt*2 + (tid>>5))*2048 + h*DV + vbase + (tid&31)];
            if (tid == 0) rs = g[bt*8 + h];
            else if (tid == 1) rs = beta[bt*16 + h*2 + 0];
            else if (tid == 2) rs = beta[bt*16 + h*2 + 1];
        }

        float kk0[8], kk1[8], qq[8];
        #pragma unroll
        for (int i=0;i<8;i++){
            kk0[i] = sK[p][0][kb+i];
            kk1[i] = sK[p][1][kb+i];
            qq[i]  = sQ[p][kb+i];
        }
        float dec = expf(sS[p][0]);
        float b0 = sS[p][1], b1 = sS[p][2];

        float p00=0.f,p01=0.f,p10=0.f,p11=0.f,q0=0.f,q1=0.f,skk=0.f,sqk0=0.f,sqk1=0.f;
        #pragma unroll
        for (int i=0;i<8;i++){
            p00 += kk0[i]*S[i][0]; p01 += kk0[i]*S[i][1];
            p10 += kk1[i]*S[i][0]; p11 += kk1[i]*S[i][1];
            q0  += qq[i] *S[i][0]; q1  += qq[i] *S[i][1];
            skk += kk1[i]*kk0[i];  sqk0 += qq[i]*kk0[i]; sqk1 += qq[i]*kk1[i];
        }
        #pragma unroll
        for (int m=1;m<16;m<<=1){
            p00 += __shfl_xor_sync(0xffffffffu, p00, m);
            p01 += __shfl_xor_sync(0xffffffffu, p01, m);
            p10 += __shfl_xor_sync(0xffffffffu, p10, m);
            p11 += __shfl_xor_sync(0xffffffffu, p11, m);
            q0  += __shfl_xor_sync(0xffffffffu, q0,  m);
            q1  += __shfl_xor_sync(0xffffffffu, q1,  m);
            skk += __shfl_xor_sync(0xffffffffu, skk, m);
            sqk0+= __shfl_xor_sync(0xffffffffu, sqk0,m);
            sqk1+= __shfl_xor_sync(0xffffffffu, sqk1,m);
        }
        float v00 = sV[p][0][vg*2+0], v01 = sV[p][0][vg*2+1];
        float v10 = sV[p][1][vg*2+0], v11 = sV[p][1][vg*2+1];
        float d00 = b0*(v00 - dec*p00);
        float d01 = b0*(v01 - dec*p01);
        float d10 = b1*(v10 - (dec*p10 + skk*d00));
        float d11 = b1*(v11 - (dec*p11 + skk*d01));
        float o0 = dec*q0 + sqk0*d00 + sqk1*d10;
        float o1 = dec*q1 + sqk0*d01 + sqk1*d11;
        #pragma unroll
        for (int i=0;i<8;i++){
            S[i][0] = dec*S[i][0] + kk0[i]*d00 + kk1[i]*d10;
            S[i][1] = dec*S[i][1] + kk0[i]*d01 + kk1[i]*d11;
        }
        if (dkg == 0){
            size_t ob = ((size_t)b*Tt + t)*2048 + h*DV + vbase + vg*2;
            o[ob]   = o0;
            o[ob+1] = o1;
        }
    }
}

// ---------------- o-norm * silu(gate) -> fp16 ----------------
__global__ void ogate_kernel(const float* __restrict__ o, const float* __restrict__ qkvg,
                             const float* __restrict__ onw, __half* __restrict__ o2){
    __shared__ float sh[8];
    int bt = blockIdx.x, h = blockIdx.y, vv = threadIdx.x;
    size_t idx = (size_t)bt*2048 + h*DV + vv;
    float val = o[idx];
    float tot = block_reduce_sum(val*val, sh);
    float scale = rsqrtf(tot/(float)DV + 1e-6f);
    float gt = qkvg[(size_t)bt*NQ2 + 7168 + h*DV + vv];
    float res = val*scale*onw[vv]*siluf_(gt);
    o2[idx] = __float2half_rn(res);
}

// ---------------- launch ----------------
extern "C" void kernel_launch(void* const* d_in, const int* in_sizes, int n_in,
                              void* d_out, int out_size){
    const float* hs         = (const float*)d_in[0];
    const float* attn_nw    = (const float*)d_in[1];
    const float* Wq         = (const float*)d_in[2];
    const float* Wk         = (const float*)d_in[3];
    const float* Wv         = (const float*)d_in[4];
    const float* Wb         = (const float*)d_in[5];
    const float* Wa         = (const float*)d_in[6];
    const float* A_log      = (const float*)d_in[7];
    const float* dt_bias    = (const float*)d_in[8];
    const float* conv_q_w   = (const float*)d_in[9];
    const float* conv_k_w   = (const float*)d_in[10];
    const float* conv_v_w   = (const float*)d_in[11];
    const float* Wg         = (const float*)d_in[12];
    const float* o_norm_w   = (const float*)d_in[13];
    const float* Wo         = (const float*)d_in[14];
    const float* mlp_norm_w = (const float*)d_in[15];
    const float* Wgate      = (const float*)d_in[16];
    const float* Wdown      = (const float*)d_in[17];

    float *qkvg,*qb,*kb,*vb,*betab,*gb,*ob,*hid;
    cudaGetSymbolAddress((void**)&qkvg, g_qkvg);
    cudaGetSymbolAddress((void**)&qb,   g_q);
    cudaGetSymbolAddress((void**)&kb,   g_k);
    cudaGetSymbolAddress((void**)&vb,   g_v);
    cudaGetSymbolAddress((void**)&betab,g_beta);
    cudaGetSymbolAddress((void**)&gb,   g_gdec);
    cudaGetSymbolAddress((void**)&ob,   g_o);
    cudaGetSymbolAddress((void**)&hid,  g_hid);

    __half *x2,*y2,*o2,*mlp2,*wqkvg2,*wo2,*wgate2,*wdown2;
    cudaGetSymbolAddress((void**)&x2,    g2_x);
    cudaGetSymbolAddress((void**)&y2,    g2_y);
    cudaGetSymbolAddress((void**)&o2,    g2_o);
    cudaGetSymbolAddress((void**)&mlp2,  g2_mlp);
    cudaGetSymbolAddress((void**)&wqkvg2,g2_Wqkvg);
    cudaGetSymbolAddress((void**)&wo2,   g2_Wo);
    cudaGetSymbolAddress((void**)&wgate2,g2_Wgate);
    cudaGetSymbolAddress((void**)&wdown2,g2_Wdown);

    cudaFuncSetAttribute(mma_gemm, cudaFuncAttributeMaxDynamicSharedMemorySize, GEMM_SMEM);

    // weight conversions into fused/transposed fp16 layouts
    w3_kernel <<<dim3( 32,32),256>>>(Wq,    wqkvg2,                        1024, 1024);
    w3_kernel <<<dim3( 64,32),256>>>(Wk,    wqkvg2 + (size_t)1024*1024,    1024, 2048);
    w3_kernel <<<dim3(128,32),256>>>(Wv,    wqkvg2 + (size_t)3072*1024,    1024, 4096);
    w3_kernel <<<dim3( 64,32),256>>>(Wg,    wqkvg2 + (size_t)7168*1024,    1024, 2048);
    w3b_kernel<<<24,256>>>(Wb, Wa, wqkvg2);
    rmsnorm_kernel<<<BT, 256>>>(hs, attn_nw, x2, Dd);

    // fused QKVG+beta+g projection (one GEMM, N=9344, Kp=1024)
    mma_gemm<<<dim3(73,32),256,GEMM_SMEM>>>(x2, wqkvg2, qkvg, nullptr, nullptr, BT, NQ2, 1024);

    // beta/g nonlinearities from fused output
    betag_post<<<BT,32>>>(qkvg, A_log, dt_bias, betab, gb);

    // remaining weight conversions (independent; before their consumer GEMMs)
    w3_kernel <<<dim3( 32,64),256>>>(Wo,    wo2,    2048, 1024);
    w3i_kernel<<<dim3(176,32),256>>>(Wgate, wgate2, 1024, 5632);
    w3_kernel <<<dim3( 32,88),256>>>(Wdown, wdown2, 2816, 1024);

    // causal conv + silu (+ l2norm for q,k), 4 timesteps per block
    conv_silu4_kernel<<<dim3( 8,Tt/4,Bb),128>>>(qkvg, conv_q_w, qb, NQ2,    0, 1024, 1);
    conv_silu4_kernel<<<dim3(16,Tt/4,Bb),128>>>(qkvg, conv_k_w, kb, NQ2, 1024, 2048, 1);
    conv_silu4_kernel<<<dim3(32,Tt/4,Bb),128>>>(qkvg, conv_v_w, vb, NQ2, 3072, 4096, 0);

    // gated delta-product recurrence (8 DV-chunks)
    scan_kernel<<<dim3(8,8,2),256>>>(qb, kb, vb, betab, gb, ob);

    // o = rmsnorm(o)*silu(gate) -> fp16, then Wo + residual (Kp=2048)
    ogate_kernel<<<dim3(BT,Hh),256>>>(ob, qkvg, o_norm_w, o2);
    mma_gemm<<<dim3( 8,32),256,GEMM_SMEM>>>(o2, wo2, hid, hs, nullptr, BT, 1024, 2048);

    // MLP: Wgate GEMM with fused swiglu -> mlp2 (Kp=1024), then Wdown (Kp=2816)
    rmsnorm_kernel<<<BT,256>>>(hid, mlp_norm_w, y2, Dd);
    mma_gemm<<<dim3(44,32),256,GEMM_SMEM>>>(y2, wgate2, nullptr, nullptr, mlp2, BT, 5632, 1024);
    mma_gemm<<<dim3( 8,32),256,GEMM_SMEM>>>(mlp2, wdown2, (float*)d_out, hid, nullptr, BT, 1024, 2816);
}